// round 11
// baseline (speedup 1.0000x reference)
#include <cuda_runtime.h>

#define BB 8
#define PP 12000
#define NP (BB*PP)
#define XN_ 144
#define CELLS (144*144)
#define NC (BB*CELLS)
#define NBLK 456
#define NWARPS (NBLK*8)
#define ROWP 10   // padded pillar row: 9 floats + 1 pad (keeps LDS.64 aligned)

// per-(batch,cell) winning pillar index (last write wins == max p)
__device__ int g_winner[NC];
// dense per-cell features, channel-major: g_feat[(b*CELLS+cell)*64 + c]
__device__ float g_feat[(size_t)NC * 64];

__global__ void k_init() {
    int i = blockIdx.x * blockDim.x + threadIdx.x;
    if (i < NC) g_winner[i] = -1;
}
__global__ void k_dummy() {}   // launch-pattern padding so ncu -s 5 hits k_compute

__global__ void k_winner(const int* __restrict__ idx) {
    int i = blockIdx.x * blockDim.x + threadIdx.x;   // grid sized exactly NP
    int y = idx[i * 3 + 1];
    int x = idx[i * 3 + 2];
    x = min(max(x, 0), 143);
    y = min(max(y, 0), 143);
    int b = i / PP;
    int p = i - b * PP;
    atomicMax(&g_winner[b * CELLS + y * XN_ + x], p);
}

__device__ __forceinline__ unsigned long long fma2(unsigned long long a,
                                                   unsigned long long b,
                                                   unsigned long long c) {
    unsigned long long d;
    asm("fma.rn.f32x2 %0, %1, %2, %3;" : "=l"(d) : "l"(a), "l"(b), "l"(c));
    return d;
}
__device__ __forceinline__ unsigned long long pack2(float lo, float hi) {
    unsigned long long d;
    asm("mov.b64 %0, {%1, %2};" : "=l"(d) : "f"(lo), "f"(hi));
    return d;
}
__device__ __forceinline__ void unpack2(unsigned long long v, float& lo, float& hi) {
    asm("mov.b64 {%0, %1}, %2;" : "=f"(lo), "=f"(hi) : "l"(v));
}
__device__ __forceinline__ unsigned smaddr(const void* p) {
    unsigned r;
    asm("{ .reg .u64 t; cvta.to.shared.u64 t, %1; cvt.u32.u64 %0, t; }"
        : "=r"(r) : "l"(p));
    return r;
}
// Copy one pillar (288 floats) global->shared into row-padded [32][ROWP]
// layout via 9 cp.async.4 per lane (4B chunks: both ends 4B-aligned).
__device__ __forceinline__ void cp_pillar(unsigned sbase, const float* g, int lane) {
    #pragma unroll
    for (int k = 0; k < 9; k++) {
        const int i = lane + 32 * k;
        const int m = i / 9;
        const int f = i - 9 * m;
        asm volatile("cp.async.ca.shared.global [%0], [%1], 4;"
                     :: "r"(sbase + (m * ROWP + f) * 4), "l"(g + i));
    }
}

// Persistent kernel over the CELL space. One warp per cell (grid-stride);
// empty cells (winner == -1) cost ~1 uniform LDG and skip.
// Lane = (cg, mg): cg = lane>>1 owns channels [4cg, 4cg+4)  (16 groups),
//                  mg = lane&1  owns m-points  [16mg, 16mg+16).
// f-PAIR packing: acc[c] += (x_f,x_f+1)*(w_c_f,w_c_f+1) via FFMA2 on x read
// directly as LDS.64 from the raw (row-padded) layout — no transpose, no
// splat MOVs. Weights = 4ch x (4 u64 pairs + f8 scalar) = 36 regs -> 3 blocks.
__global__ void __launch_bounds__(256, 3) k_compute(
    const float* __restrict__ pillars,
    const float* __restrict__ cw,
    const float* __restrict__ gamma,
    const float* __restrict__ beta,
    const float* __restrict__ mean,
    const float* __restrict__ var)
{
    __shared__ __align__(16) float sm[8][2][32 * ROWP];
    const int wlocal = threadIdx.x >> 5;
    const int lane   = threadIdx.x & 31;
    const int cg     = lane >> 1;
    const int mg     = lane & 1;

    // Per-warp constants: f-pair-packed weights for this lane's 4 channels
    unsigned long long wf[4][4];
    float w8[4];
    #pragma unroll
    for (int ch = 0; ch < 4; ch++) {
        const float* w = cw + (cg * 4 + ch) * 9;
        #pragma unroll
        for (int fp = 0; fp < 4; fp++)
            wf[ch][fp] = pack2(w[2 * fp], w[2 * fp + 1]);
        w8[ch] = w[8];
    }
    const int cs = cg * 4 + mg * 2;   // the 2 channels this lane stores
    const float s0 = gamma[cs]     * rsqrtf(var[cs]     + 1e-5f);
    const float s1 = gamma[cs + 1] * rsqrtf(var[cs + 1] + 1e-5f);
    const float b0 = beta[cs]     - mean[cs]     * s0;
    const float b1 = beta[cs + 1] - mean[cs + 1] * s1;

    unsigned sbuf0 = smaddr(&sm[wlocal][0][0]);
    unsigned sbuf1 = smaddr(&sm[wlocal][1][0]);

    int cell = (blockIdx.x * blockDim.x + threadIdx.x) >> 5;
    if (cell >= NC) return;

    int wcur = g_winner[cell];
    if (wcur >= 0)
        cp_pillar(sbuf0, pillars + ((size_t)(cell / CELLS) * PP + wcur) * 288, lane);
    asm volatile("cp.async.commit_group;");
    int pb = 0;

    for (; cell < NC; cell += NWARPS) {
        __syncwarp();   // all lanes aligned before buffer pb may be refilled

        // Prefetch next cell's winner + pillar into the other buffer
        const int ncell = cell + NWARPS;
        const int wnext = (ncell < NC) ? g_winner[ncell] : -1;
        if (wnext >= 0)
            cp_pillar(pb ? sbuf0 : sbuf1,
                      pillars + ((size_t)(ncell / CELLS) * PP + wnext) * 288, lane);
        asm volatile("cp.async.commit_group;");

        if (wcur >= 0) {
            asm volatile("cp.async.wait_group 1;");   // current buffer ready
            __syncwarp();
            const float* buf = &sm[wlocal][pb][0];

            float mx0 = -3.402823466e38f, mx1 = mx0, mx2 = mx0, mx3 = mx0;
            #pragma unroll
            for (int mi = 0; mi < 16; mi++) {
                const float* xr = buf + (16 * mg + mi) * ROWP;
                // f-pairs as LDS.64 (aligned: row offset is a multiple of 8B)
                const unsigned long long x01 = *reinterpret_cast<const unsigned long long*>(xr + 0);
                const unsigned long long x23 = *reinterpret_cast<const unsigned long long*>(xr + 2);
                const unsigned long long x45 = *reinterpret_cast<const unsigned long long*>(xr + 4);
                const unsigned long long x67 = *reinterpret_cast<const unsigned long long*>(xr + 6);
                const float x8 = xr[8];

                unsigned long long a0 = fma2(x01, wf[0][0], 0ull);
                unsigned long long a1 = fma2(x01, wf[1][0], 0ull);
                unsigned long long a2 = fma2(x01, wf[2][0], 0ull);
                unsigned long long a3 = fma2(x01, wf[3][0], 0ull);
                a0 = fma2(x23, wf[0][1], a0);  a1 = fma2(x23, wf[1][1], a1);
                a2 = fma2(x23, wf[2][1], a2);  a3 = fma2(x23, wf[3][1], a3);
                a0 = fma2(x45, wf[0][2], a0);  a1 = fma2(x45, wf[1][2], a1);
                a2 = fma2(x45, wf[2][2], a2);  a3 = fma2(x45, wf[3][2], a3);
                a0 = fma2(x67, wf[0][3], a0);  a1 = fma2(x67, wf[1][3], a1);
                a2 = fma2(x67, wf[2][3], a2);  a3 = fma2(x67, wf[3][3], a3);

                float lo, hi;
                unpack2(a0, lo, hi); mx0 = fmaxf(mx0, fmaf(x8, w8[0], lo) + hi);
                unpack2(a1, lo, hi); mx1 = fmaxf(mx1, fmaf(x8, w8[1], lo) + hi);
                unpack2(a2, lo, hi); mx2 = fmaxf(mx2, fmaf(x8, w8[2], lo) + hi);
                unpack2(a3, lo, hi); mx3 = fmaxf(mx3, fmaf(x8, w8[3], lo) + hi);
            }

            // Merge the two m-halves (partner lane = lane^1)
            mx0 = fmaxf(mx0, __shfl_xor_sync(0xFFFFFFFFu, mx0, 1));
            mx1 = fmaxf(mx1, __shfl_xor_sync(0xFFFFFFFFu, mx1, 1));
            mx2 = fmaxf(mx2, __shfl_xor_sync(0xFFFFFFFFu, mx2, 1));
            mx3 = fmaxf(mx3, __shfl_xor_sync(0xFFFFFFFFu, mx3, 1));

            // BN+ReLU once on the raw max (scale>0, monotone => exact)
            const float ra = mg ? mx2 : mx0;
            const float rb = mg ? mx3 : mx1;
            const float fA = fmaxf(fmaf(ra, s0, b0), 0.0f);
            const float fB = fmaxf(fmaf(rb, s1, b1), 0.0f);
            // Dense channel-major store: warp covers 64 consecutive floats
            reinterpret_cast<float2*>(g_feat + ((size_t)cell << 6))[lane] =
                make_float2(fA, fB);
        }

        wcur = wnext;
        pb ^= 1;
    }
}

// Transpose g_feat [b][cell][c] -> out [b][c][cell], writing zeros for empty
// cells (also replaces the output memset). Tile = 32 cells x 64 channels.
__global__ void __launch_bounds__(256) k_transpose(float* __restrict__ out) {
    __shared__ float ts[64][33];
    __shared__ int win[32];
    const int t     = threadIdx.x;
    const int b     = blockIdx.y;
    const int cell0 = blockIdx.x * 32;

    if (t < 32) win[t] = g_winner[b * CELLS + cell0 + t];
    __syncthreads();

    {
        const int c = t & 63;
        #pragma unroll
        for (int k = 0; k < 8; k++) {
            const int cl = (t >> 6) + k * 4;
            float v = 0.0f;
            if (win[cl] >= 0)
                v = g_feat[(((size_t)(b * CELLS + cell0 + cl)) << 6) + c];
            ts[c][cl] = v;
        }
    }
    __syncthreads();
    {
        const int cl = t & 31;
        #pragma unroll
        for (int k = 0; k < 8; k++) {
            const int c = (t >> 5) + k * 8;
            out[((size_t)(b * 64 + c)) * CELLS + cell0 + cl] = ts[c][cl];
        }
    }
}

extern "C" void kernel_launch(void* const* d_in, const int* in_sizes, int n_in,
                              void* d_out, int out_size) {
    const float* pillars = (const float*)d_in[0];
    const int*   idx     = (const int*)d_in[1];
    const float* cw      = (const float*)d_in[2];
    const float* gamma   = (const float*)d_in[3];
    const float* beta    = (const float*)d_in[4];
    const float* mean    = (const float*)d_in[5];
    const float* var     = (const float*)d_in[6];
    float* out = (float*)d_out;

    // 7-kernel pattern: ncu -s 5 -c 1 deterministically profiles k_compute.
    k_init<<<(NC + 255) / 256, 256>>>();
    k_winner<<<NP / 256, 256>>>(idx);
    k_dummy<<<1, 32>>>();
    k_dummy<<<1, 32>>>();
    k_dummy<<<1, 32>>>();
    k_compute<<<NBLK, 256>>>(pillars, cw, gamma, beta, mean, var);
    k_transpose<<<dim3(CELLS / 32, BB), 256>>>(out);
}

// round 12
// speedup vs baseline: 1.1622x; 1.1622x over previous
#include <cuda_runtime.h>

#define BB 8
#define PP 12000
#define NP (BB*PP)
#define XN_ 144
#define CELLS (144*144)
#define NC (BB*CELLS)
#define NBLK 456
#define NWARPS (NBLK*8)

// per-(batch,cell) winning pillar index (last write wins == max p)
__device__ int g_winner[NC];
// dense per-cell features, channel-major: g_feat[(b*CELLS+cell)*64 + c]
__device__ float g_feat[(size_t)NC * 64];

__global__ void k_winner(const int* __restrict__ idx) {
    int i = blockIdx.x * blockDim.x + threadIdx.x;   // grid sized exactly NP
    int y = idx[i * 3 + 1];
    int x = idx[i * 3 + 2];
    x = min(max(x, 0), 143);
    y = min(max(y, 0), 143);
    int b = i / PP;
    int p = i - b * PP;
    atomicMax(&g_winner[b * CELLS + y * XN_ + x], p);
}

__device__ __forceinline__ unsigned long long fma2(unsigned long long a,
                                                   unsigned long long b,
                                                   unsigned long long c) {
    unsigned long long d;
    asm("fma.rn.f32x2 %0, %1, %2, %3;" : "=l"(d) : "l"(a), "l"(b), "l"(c));
    return d;
}
__device__ __forceinline__ unsigned long long splat2(float s) {
    unsigned long long d;
    asm("mov.b64 %0, {%1, %1};" : "=l"(d) : "f"(s));
    return d;
}
__device__ __forceinline__ unsigned long long pack2(float lo, float hi) {
    unsigned long long d;
    asm("mov.b64 %0, {%1, %2};" : "=l"(d) : "f"(lo), "f"(hi));
    return d;
}
__device__ __forceinline__ void unpack2(unsigned long long v, float& lo, float& hi) {
    asm("mov.b64 {%0, %1}, %2;" : "=f"(lo), "=f"(hi) : "l"(v));
}
__device__ __forceinline__ unsigned smaddr(const void* p) {
    unsigned r;
    asm("{ .reg .u64 t; cvta.to.shared.u64 t, %1; cvt.u32.u64 %0, t; }"
        : "=r"(r) : "l"(p));
    return r;
}
// Copy one 1152-byte pillar global->shared via cp.async (72 x 16B chunks).
__device__ __forceinline__ void cp_pillar(unsigned sbase, const float* g, int lane) {
    asm volatile("cp.async.cg.shared.global [%0], [%1], 16;"
                 :: "r"(sbase + lane * 16), "l"(g + lane * 4));
    asm volatile("cp.async.cg.shared.global [%0], [%1], 16;"
                 :: "r"(sbase + (lane + 32) * 16), "l"(g + (lane + 32) * 4));
    if (lane < 8)
        asm volatile("cp.async.cg.shared.global [%0], [%1], 16;"
                     :: "r"(sbase + (lane + 64) * 16), "l"(g + (lane + 64) * 4));
}

// Persistent kernel over the CELL space. One warp per cell (grid-stride);
// empty cells (winner == -1) cost ~1 uniform LDG and skip.
// Lane = (cg, mg): cg = lane>>1 owns channels [4cg, 4cg+4)  (16 groups),
//                  mg = lane&1  owns m-points  [16mg, 16mg+16).
// CHANNEL-pair packing (uniform over all 9 f — no odd tail): per f, x is
// splatted once and feeds 2 FFMA2 (4 channels). Weights = wp[9][2] = 36 regs
// -> ~65 regs total -> 3 blocks/SM = 24 warps/SM (vs 16 for 8ch/lane).
__global__ void __launch_bounds__(256, 3) k_compute(
    const float* __restrict__ pillars,
    const float* __restrict__ cw,
    const float* __restrict__ gamma,
    const float* __restrict__ beta,
    const float* __restrict__ mean,
    const float* __restrict__ var)
{
    __shared__ __align__(16) float sm[8][2][288];
    const int wlocal = threadIdx.x >> 5;
    const int lane   = threadIdx.x & 31;
    const int cg     = lane >> 1;
    const int mg     = lane & 1;

    // Per-warp constants: wp[f][p] = (w[4cg+2p][f], w[4cg+2p+1][f])
    unsigned long long wp[9][2];
    #pragma unroll
    for (int p = 0; p < 2; p++) {
        const float* w0 = cw + (cg * 4 + 2 * p) * 9;
        #pragma unroll
        for (int f = 0; f < 9; f++)
            wp[f][p] = pack2(w0[f], w0[9 + f]);
    }
    const int cs = cg * 4 + mg * 2;   // the 2 channels this lane stores (= lane*2)
    const float s0 = gamma[cs]     * rsqrtf(var[cs]     + 1e-5f);
    const float s1 = gamma[cs + 1] * rsqrtf(var[cs + 1] + 1e-5f);
    const float b0 = beta[cs]     - mean[cs]     * s0;
    const float b1 = beta[cs + 1] - mean[cs + 1] * s1;

    unsigned sbuf0 = smaddr(&sm[wlocal][0][0]);
    unsigned sbuf1 = smaddr(&sm[wlocal][1][0]);

    int cell = (blockIdx.x * blockDim.x + threadIdx.x) >> 5;
    if (cell >= NC) return;

    int wcur = g_winner[cell];
    if (wcur >= 0)
        cp_pillar(sbuf0, pillars + ((size_t)(cell / CELLS) * PP + wcur) * 288, lane);
    asm volatile("cp.async.commit_group;");
    int pb = 0;

    for (; cell < NC; cell += NWARPS) {
        __syncwarp();   // all lanes aligned before buffer pb may be refilled

        // Prefetch next cell's winner + pillar into the other buffer
        const int ncell = cell + NWARPS;
        const int wnext = (ncell < NC) ? g_winner[ncell] : -1;
        if (wnext >= 0)
            cp_pillar(pb ? sbuf0 : sbuf1,
                      pillars + ((size_t)(ncell / CELLS) * PP + wnext) * 288, lane);
        asm volatile("cp.async.commit_group;");

        if (wcur >= 0) {
            asm volatile("cp.async.wait_group 1;");   // current buffer ready
            __syncwarp();
            const float* buf = &sm[wlocal][pb][0];

            float mx0 = -3.402823466e38f, mx1 = mx0, mx2 = mx0, mx3 = mx0;
            #pragma unroll
            for (int mi = 0; mi < 16; mi++) {
                const float* xr = buf + (16 * mg + mi) * 9;
                unsigned long long a0 = 0ull, a1 = 0ull;
                #pragma unroll
                for (int f = 0; f < 9; f++) {
                    const unsigned long long xs = splat2(xr[f]);
                    a0 = fma2(xs, wp[f][0], a0);
                    a1 = fma2(xs, wp[f][1], a1);
                }
                float lo, hi;
                unpack2(a0, lo, hi); mx0 = fmaxf(mx0, lo); mx1 = fmaxf(mx1, hi);
                unpack2(a1, lo, hi); mx2 = fmaxf(mx2, lo); mx3 = fmaxf(mx3, hi);
            }

            // Merge the two m-halves (partner lane = lane^1)
            mx0 = fmaxf(mx0, __shfl_xor_sync(0xFFFFFFFFu, mx0, 1));
            mx1 = fmaxf(mx1, __shfl_xor_sync(0xFFFFFFFFu, mx1, 1));
            mx2 = fmaxf(mx2, __shfl_xor_sync(0xFFFFFFFFu, mx2, 1));
            mx3 = fmaxf(mx3, __shfl_xor_sync(0xFFFFFFFFu, mx3, 1));

            // BN+ReLU once on the raw max (scale>0, monotone => exact)
            const float ra = mg ? mx2 : mx0;
            const float rb = mg ? mx3 : mx1;
            const float fA = fmaxf(fmaf(ra, s0, b0), 0.0f);
            const float fB = fmaxf(fmaf(rb, s1, b1), 0.0f);
            // Dense channel-major store: warp covers 64 consecutive floats
            reinterpret_cast<float2*>(g_feat + ((size_t)cell << 6))[lane] =
                make_float2(fA, fB);
        }

        wcur = wnext;
        pb ^= 1;
    }
}

// Transpose g_feat [b][cell][c] -> out [b][c][cell], writing zeros for empty
// cells (also replaces the output memset). Tile = 32 cells x 64 channels.
__global__ void __launch_bounds__(256) k_transpose(float* __restrict__ out) {
    __shared__ float ts[64][33];
    __shared__ int win[32];
    const int t     = threadIdx.x;
    const int b     = blockIdx.y;
    const int cell0 = blockIdx.x * 32;

    if (t < 32) win[t] = g_winner[b * CELLS + cell0 + t];
    __syncthreads();

    {
        const int c = t & 63;
        #pragma unroll
        for (int k = 0; k < 8; k++) {
            const int cl = (t >> 6) + k * 4;
            float v = 0.0f;
            if (win[cl] >= 0)
                v = g_feat[(((size_t)(b * CELLS + cell0 + cl)) << 6) + c];
            ts[c][cl] = v;
        }
    }
    __syncthreads();
    {
        const int cl = t & 31;
        #pragma unroll
        for (int k = 0; k < 8; k++) {
            const int c = (t >> 5) + k * 8;
            out[((size_t)(b * 64 + c)) * CELLS + cell0 + cl] = ts[c][cl];
        }
    }
}

extern "C" void kernel_launch(void* const* d_in, const int* in_sizes, int n_in,
                              void* d_out, int out_size) {
    const float* pillars = (const float*)d_in[0];
    const int*   idx     = (const int*)d_in[1];
    const float* cw      = (const float*)d_in[2];
    const float* gamma   = (const float*)d_in[3];
    const float* beta    = (const float*)d_in[4];
    const float* mean    = (const float*)d_in[5];
    const float* var     = (const float*)d_in[6];
    float* out = (float*)d_out;

    void* winner_ptr = nullptr;
    cudaGetSymbolAddress(&winner_ptr, g_winner);

    cudaMemsetAsync(winner_ptr, 0xFF, sizeof(int) * NC, 0);  // -1
    k_winner<<<NP / 256, 256>>>(idx);
    k_compute<<<NBLK, 256>>>(pillars, cw, gamma, beta, mean, var);
    k_transpose<<<dim3(CELLS / 32, BB), 256>>>(out);
}